// round 17
// baseline (speedup 1.0000x reference)
#include <cuda_runtime.h>
#include <cuda_bf16.h>
#include <cstdint>

#define MAXN  100000
#define MAXE  2000000
#define DH    256
#define DIN   128

// Scratch (static device globals — no allocation allowed)
__device__ float g_dinv[MAXN];
__device__ float g_buf2[(size_t)MAXN * DH];
__device__ int   g_cnt[MAXN];
__device__ int   g_off[MAXN + 1];
__device__ int   g_cur[MAXN];
__device__ int   g_src[MAXE];
__device__ float g_wt1[DH * DIN];   // W1^T [256][128]
__device__ float g_wt2[DH * DH];    // W2^T [256][256]

// ---------------------------------------------------------------------------
// CSR build
// ---------------------------------------------------------------------------
__global__ void count_kernel(const int* __restrict__ edst, int e, int* __restrict__ cnt) {
    int i = blockIdx.x * blockDim.x + threadIdx.x;
    if (i < e) atomicAdd(&cnt[edst[i]], 1);
}

__global__ void __launch_bounds__(1024)
scan_kernel(const int* __restrict__ cnt, int* __restrict__ off, int* __restrict__ cur,
            float* __restrict__ dinv, int n) {
    __shared__ int ssum[1024];
    const int tid = threadIdx.x;
    const int chunk = (n + 1023) >> 10;
    const int begin = tid * chunk;
    const int end   = min(begin + chunk, n);

    int mysum = 0;
    for (int i = begin; i < end; i++) mysum += cnt[i];
    ssum[tid] = mysum;
    __syncthreads();
    for (int d = 1; d < 1024; d <<= 1) {
        int add = (tid >= d) ? ssum[tid - d] : 0;
        __syncthreads();
        ssum[tid] += add;
        __syncthreads();
    }
    int run = ssum[tid] - mysum;
    for (int i = begin; i < end; i++) {
        int c = cnt[i];
        off[i] = run;
        cur[i] = run;
        dinv[i] = rsqrtf(1.0f + (float)c);
        run += c;
    }
    if (tid == 1023) off[n] = ssum[1023];
}

__global__ void fill_kernel(const int* __restrict__ esrc, const int* __restrict__ edst,
                            int e, int* __restrict__ cur, int* __restrict__ sorted) {
    int i = blockIdx.x * blockDim.x + threadIdx.x;
    if (i < e) {
        int d = edst[i];
        int pos = atomicAdd(&cur[d], 1);
        sorted[pos] = esrc[i];
    }
}

// ---------------------------------------------------------------------------
// Transpose W [K][256] -> Wt [256][K]
// ---------------------------------------------------------------------------
template <int K>
__global__ void transpose_kernel(const float* __restrict__ W, float* __restrict__ Wt) {
    __shared__ float t[32][33];
    int bx = blockIdx.x * 32;
    int by = blockIdx.y * 32;
#pragma unroll
    for (int i = 0; i < 4; i++)
        t[threadIdx.y + i * 8][threadIdx.x] =
            W[(size_t)(by + threadIdx.y + i * 8) * DH + bx + threadIdx.x];
    __syncthreads();
#pragma unroll
    for (int i = 0; i < 4; i++)
        Wt[(size_t)(bx + threadIdx.y + i * 8) * K + by + threadIdx.x] =
            t[threadIdx.x][threadIdx.y + i * 8];
}

// ---------------------------------------------------------------------------
// bf16 split helpers (3-term split: x = hi + lo + O(2^-18 x))
// ---------------------------------------------------------------------------
__device__ __forceinline__ uint32_t bpack(__nv_bfloat16 a, __nv_bfloat16 b) {
    __nv_bfloat162 p(a, b);
    return *reinterpret_cast<uint32_t*>(&p);
}
__device__ __forceinline__ void split2(float f0, float f1, uint32_t& h, uint32_t& l) {
    __nv_bfloat16 h0 = __float2bfloat16(f0);
    __nv_bfloat16 h1 = __float2bfloat16(f1);
    __nv_bfloat16 l0 = __float2bfloat16(f0 - __bfloat162float(h0));
    __nv_bfloat16 l1 = __float2bfloat16(f1 - __bfloat162float(h1));
    h = bpack(h0, h1);
    l = bpack(l0, l1);
}

__device__ __forceinline__ void mma_bf16(float* c, const uint32_t* a, uint32_t b0, uint32_t b1) {
    asm volatile(
        "mma.sync.aligned.m16n8k16.row.col.f32.bf16.bf16.f32 "
        "{%0,%1,%2,%3}, {%4,%5,%6,%7}, {%8,%9}, {%0,%1,%2,%3};"
        : "+f"(c[0]), "+f"(c[1]), "+f"(c[2]), "+f"(c[3])
        : "r"(a[0]), "r"(a[1]), "r"(a[2]), "r"(a[3]), "r"(b0), "r"(b1));
}

// ---------------------------------------------------------------------------
// FUSED gather + tensor-core GEMM (one kernel per GCN layer).
// Phase 1: 8 warps gather the CTA's 64 z-rows (CSR by destination), convert
//          to split-bf16 fragment layout DIRECTLY in smem (z never hits DRAM).
// Phase 2: bf16 m16n8k16 x 3-term GEMM; A full-K resident in smem; B single-
//          buffered with register-staged prefetch.
//   LAYER 1 (K=128): z = dd*(sum ds*x[s] + dd*x[d]);  C = dinv*relu(zW1+b1)
//   LAYER 2 (K=256): z = dd*(sum hs[s] + hs[d]);      C = relu(zW2+b2)
// A smem stride S = K/2+4 words (S mod 32 == 4 -> fragment LDS bank 4g+t,
// conflict-free). 2 CTAs/SM: one CTA's gather overlaps the other's MMA.
// ---------------------------------------------------------------------------
#define F1_SMEM ((2 * 64 * 68 + 2 * 3072) * 4)    // 59392 B (K=128)
#define F2_SMEM ((2 * 64 * 132 + 2 * 3072) * 4)   // 92160 B (K=256)

template <int K, int LAYER>
__global__ void __launch_bounds__(256, 2)
fused_kernel(const float* __restrict__ src, const float* __restrict__ Wt,
             const int* __restrict__ off, const int* __restrict__ srt,
             const float* __restrict__ dinv, const float* __restrict__ bias,
             float* __restrict__ C, int M) {
    constexpr int NT  = K / 16;
    constexpr int S   = K / 2 + 4;       // 68 (K=128) / 132 (K=256)
    constexpr int A_W = 64 * S;
    extern __shared__ uint32_t smw[];
    uint32_t* AsH = smw;                 // [64][S]
    uint32_t* AsL = smw + A_W;
    uint32_t* BsH = smw + 2 * A_W;       // [256][12]
    uint32_t* BsL = BsH + 3072;

    const int tid  = threadIdx.x;
    const int bm   = blockIdx.x * 64;
    const int wid  = tid >> 5;
    const int lane = tid & 31;
    const int wm   = wid >> 2;
    const int wn   = wid & 3;
    const int g    = lane >> 2;
    const int t    = lane & 3;

    // ---- stage B chunk 0 immediately (Bs untouched yet; loads overlap gather) ----
    const float* bP = &Wt[(size_t)tid * K];
    float4 bS[4];
#pragma unroll
    for (int j = 0; j < 4; j++) bS[j] = __ldg(reinterpret_cast<const float4*>(bP) + j);
    {
        uint32_t h0, l0, h1, l1;
#pragma unroll
        for (int j = 0; j < 4; j++) {
            split2(bS[j].x, bS[j].y, h0, l0);
            split2(bS[j].z, bS[j].w, h1, l1);
            *reinterpret_cast<uint2*>(&BsH[tid * 12 + j * 2]) = make_uint2(h0, h1);
            *reinterpret_cast<uint2*>(&BsL[tid * 12 + j * 2]) = make_uint2(l0, l1);
        }
    }

    // ---- Phase 1: gather 8 rows per warp into As (split-bf16) ----
    const float4* base = reinterpret_cast<const float4*>(src);
#pragma unroll 1
    for (int i = 0; i < 8; i++) {
        const int r = wid * 8 + i;
        const int d = bm + r;
        if (LAYER == 1) {
            float4 v = make_float4(0.f, 0.f, 0.f, 0.f);
            if (d < M) {
                const float dd = dinv[d];
                const int s0 = off[d];
                const int s1 = off[d + 1];
                float4 a = __ldg(base + (size_t)d * 32 + lane);
                v = make_float4(a.x * dd, a.y * dd, a.z * dd, a.w * dd);
                int j = s0;
                for (; j + 3 < s1; j += 4) {
                    int sA = __ldg(&srt[j]);
                    int sB = __ldg(&srt[j + 1]);
                    int sC = __ldg(&srt[j + 2]);
                    int sD = __ldg(&srt[j + 3]);
                    float dA = __ldg(&dinv[sA]);
                    float dB = __ldg(&dinv[sB]);
                    float dC = __ldg(&dinv[sC]);
                    float dD = __ldg(&dinv[sD]);
                    float4 rA = __ldg(base + (size_t)sA * 32 + lane);
                    float4 rB = __ldg(base + (size_t)sB * 32 + lane);
                    float4 rC = __ldg(base + (size_t)sC * 32 + lane);
                    float4 rD = __ldg(base + (size_t)sD * 32 + lane);
                    v.x = fmaf(rA.x, dA, v.x); v.y = fmaf(rA.y, dA, v.y);
                    v.z = fmaf(rA.z, dA, v.z); v.w = fmaf(rA.w, dA, v.w);
                    v.x = fmaf(rB.x, dB, v.x); v.y = fmaf(rB.y, dB, v.y);
                    v.z = fmaf(rB.z, dB, v.z); v.w = fmaf(rB.w, dB, v.w);
                    v.x = fmaf(rC.x, dC, v.x); v.y = fmaf(rC.y, dC, v.y);
                    v.z = fmaf(rC.z, dC, v.z); v.w = fmaf(rC.w, dC, v.w);
                    v.x = fmaf(rD.x, dD, v.x); v.y = fmaf(rD.y, dD, v.y);
                    v.z = fmaf(rD.z, dD, v.z); v.w = fmaf(rD.w, dD, v.w);
                }
                for (; j < s1; j++) {
                    int s = __ldg(&srt[j]);
                    float dsv = __ldg(&dinv[s]);
                    float4 rr = __ldg(base + (size_t)s * 32 + lane);
                    v.x = fmaf(rr.x, dsv, v.x); v.y = fmaf(rr.y, dsv, v.y);
                    v.z = fmaf(rr.z, dsv, v.z); v.w = fmaf(rr.w, dsv, v.w);
                }
                v.x *= dd; v.y *= dd; v.z *= dd; v.w *= dd;
            }
            uint32_t h0, l0, h1, l1;
            split2(v.x, v.y, h0, l0);
            split2(v.z, v.w, h1, l1);
            *reinterpret_cast<uint2*>(&AsH[r * S + 2 * lane]) = make_uint2(h0, h1);
            *reinterpret_cast<uint2*>(&AsL[r * S + 2 * lane]) = make_uint2(l0, l1);
        } else {
            float4 v0 = make_float4(0.f, 0.f, 0.f, 0.f);
            float4 v1 = v0;
            if (d < M) {
                const int s0 = off[d];
                const int s1 = off[d + 1];
                v0 = __ldg(base + (size_t)d * 64 + lane);
                v1 = __ldg(base + (size_t)d * 64 + 32 + lane);
                int j = s0;
                for (; j + 3 < s1; j += 4) {
                    int sA = __ldg(&srt[j]);
                    int sB = __ldg(&srt[j + 1]);
                    int sC = __ldg(&srt[j + 2]);
                    int sD = __ldg(&srt[j + 3]);
                    const float4* iA = base + (size_t)sA * 64 + lane;
                    const float4* iB = base + (size_t)sB * 64 + lane;
                    const float4* iC = base + (size_t)sC * 64 + lane;
                    const float4* iD = base + (size_t)sD * 64 + lane;
                    float4 a0 = __ldg(iA), a1 = __ldg(iA + 32);
                    float4 b0 = __ldg(iB), b1 = __ldg(iB + 32);
                    float4 c0 = __ldg(iC), c1 = __ldg(iC + 32);
                    float4 e0 = __ldg(iD), e1 = __ldg(iD + 32);
                    v0.x += (a0.x + b0.x) + (c0.x + e0.x);
                    v0.y += (a0.y + b0.y) + (c0.y + e0.y);
                    v0.z += (a0.z + b0.z) + (c0.z + e0.z);
                    v0.w += (a0.w + b0.w) + (c0.w + e0.w);
                    v1.x += (a1.x + b1.x) + (c1.x + e1.x);
                    v1.y += (a1.y + b1.y) + (c1.y + e1.y);
                    v1.z += (a1.z + b1.z) + (c1.z + e1.z);
                    v1.w += (a1.w + b1.w) + (c1.w + e1.w);
                }
                for (; j < s1; j++) {
                    int s = __ldg(&srt[j]);
                    const float4* in = base + (size_t)s * 64 + lane;
                    float4 a0 = __ldg(in), a1 = __ldg(in + 32);
                    v0.x += a0.x; v0.y += a0.y; v0.z += a0.z; v0.w += a0.w;
                    v1.x += a1.x; v1.y += a1.y; v1.z += a1.z; v1.w += a1.w;
                }
                const float dd = dinv[d];
                v0.x *= dd; v0.y *= dd; v0.z *= dd; v0.w *= dd;
                v1.x *= dd; v1.y *= dd; v1.z *= dd; v1.w *= dd;
            }
            uint32_t h0, l0, h1, l1;
            split2(v0.x, v0.y, h0, l0);
            split2(v0.z, v0.w, h1, l1);
            *reinterpret_cast<uint2*>(&AsH[r * S + 2 * lane]) = make_uint2(h0, h1);
            *reinterpret_cast<uint2*>(&AsL[r * S + 2 * lane]) = make_uint2(l0, l1);
            split2(v1.x, v1.y, h0, l0);
            split2(v1.z, v1.w, h1, l1);
            *reinterpret_cast<uint2*>(&AsH[r * S + 64 + 2 * lane]) = make_uint2(h0, h1);
            *reinterpret_cast<uint2*>(&AsL[r * S + 64 + 2 * lane]) = make_uint2(l0, l1);
        }
    }
    __syncthreads();

    // ---- Phase 2: GEMM mainloop ----
    float acc[2][8][4];
#pragma unroll
    for (int i = 0; i < 2; i++)
#pragma unroll
        for (int j = 0; j < 8; j++)
#pragma unroll
            for (int q = 0; q < 4; q++) acc[i][j][q] = 0.0f;

    for (int tt = 0; tt < NT; tt++) {
        const bool has_next = (tt + 1 < NT);
        if (has_next) {
            const int k0 = (tt + 1) * 16;
#pragma unroll
            for (int j = 0; j < 4; j++)
                bS[j] = __ldg(reinterpret_cast<const float4*>(bP + k0) + j);
        }

        const int kb = tt * 8;
        uint32_t aHf[2][4], aLf[2][4];
#pragma unroll
        for (int mt = 0; mt < 2; mt++) {
            const int r0 = (wm * 32 + mt * 16 + g) * S + kb;
            aHf[mt][0] = AsH[r0 + t];
            aHf[mt][1] = AsH[r0 + 8 * S + t];
            aHf[mt][2] = AsH[r0 + t + 4];
            aHf[mt][3] = AsH[r0 + 8 * S + t + 4];
            aLf[mt][0] = AsL[r0 + t];
            aLf[mt][1] = AsL[r0 + 8 * S + t];
            aLf[mt][2] = AsL[r0 + t + 4];
            aLf[mt][3] = AsL[r0 + 8 * S + t + 4];
        }
#pragma unroll
        for (int nt = 0; nt < 8; nt++) {
            const int nbi = (wn * 64 + nt * 8 + g) * 12;
            const uint32_t b0H = BsH[nbi + t];
            const uint32_t b1H = BsH[nbi + t + 4];
            const uint32_t b0L = BsL[nbi + t];
            const uint32_t b1L = BsL[nbi + t + 4];
#pragma unroll
            for (int mt = 0; mt < 2; mt++) {
                mma_bf16(acc[mt][nt], aHf[mt], b0L, b1L);
                mma_bf16(acc[mt][nt], aLf[mt], b0H, b1H);
                mma_bf16(acc[mt][nt], aHf[mt], b0H, b1H);
            }
        }

        if (has_next) {
            __syncthreads();
            uint32_t h0, l0, h1, l1;
#pragma unroll
            for (int j = 0; j < 4; j++) {
                split2(bS[j].x, bS[j].y, h0, l0);
                split2(bS[j].z, bS[j].w, h1, l1);
                *reinterpret_cast<uint2*>(&BsH[tid * 12 + j * 2]) = make_uint2(h0, h1);
                *reinterpret_cast<uint2*>(&BsL[tid * 12 + j * 2]) = make_uint2(l0, l1);
            }
            __syncthreads();
        }
    }

    // ---- epilogue ----
#pragma unroll
    for (int mt = 0; mt < 2; mt++) {
        const int r0 = bm + wm * 32 + mt * 16 + g;
        const int r1 = r0 + 8;
        float s0 = 1.0f, s1 = 1.0f;
        if (LAYER == 1) {
            if (r0 < M) s0 = dinv[r0];
            if (r1 < M) s1 = dinv[r1];
        }
#pragma unroll
        for (int nt = 0; nt < 8; nt++) {
            const int c0 = wn * 64 + nt * 8 + 2 * t;
            const float bb0 = bias[c0];
            const float bb1 = bias[c0 + 1];
            float v00 = fmaxf(acc[mt][nt][0] + bb0, 0.0f) * s0;
            float v01 = fmaxf(acc[mt][nt][1] + bb1, 0.0f) * s0;
            float v10 = fmaxf(acc[mt][nt][2] + bb0, 0.0f) * s1;
            float v11 = fmaxf(acc[mt][nt][3] + bb1, 0.0f) * s1;
            if (r0 < M)
                *reinterpret_cast<float2*>(&C[(size_t)r0 * DH + c0]) = make_float2(v00, v01);
            if (r1 < M)
                *reinterpret_cast<float2*>(&C[(size_t)r1 * DH + c0]) = make_float2(v10, v11);
        }
    }
}

// ---------------------------------------------------------------------------
// Launch
// ---------------------------------------------------------------------------
extern "C" void kernel_launch(void* const* d_in, const int* in_sizes, int n_in,
                              void* d_out, int out_size) {
    const float* x  = (const float*)d_in[0];
    const int*   ei = (const int*)d_in[1];
    const float* W1 = (const float*)d_in[2];
    const float* b1 = (const float*)d_in[3];
    const float* W2 = (const float*)d_in[4];
    const float* b2 = (const float*)d_in[5];
    float* out = (float*)d_out;

    const int n = in_sizes[0] / DIN;
    const int e = in_sizes[1] / 2;
    const int* esrc = ei;
    const int* edst = ei + e;

    float *dinv, *buf2, *wt1, *wt2;
    int *cnt, *off, *cur, *srt;
    cudaGetSymbolAddress((void**)&dinv, g_dinv);
    cudaGetSymbolAddress((void**)&buf2, g_buf2);
    cudaGetSymbolAddress((void**)&cnt,  g_cnt);
    cudaGetSymbolAddress((void**)&off,  g_off);
    cudaGetSymbolAddress((void**)&cur,  g_cur);
    cudaGetSymbolAddress((void**)&srt,  g_src);
    cudaGetSymbolAddress((void**)&wt1,  g_wt1);
    cudaGetSymbolAddress((void**)&wt2,  g_wt2);

    cudaFuncSetAttribute(fused_kernel<DIN, 1>, cudaFuncAttributeMaxDynamicSharedMemorySize, F1_SMEM);
    cudaFuncSetAttribute(fused_kernel<DH, 2>,  cudaFuncAttributeMaxDynamicSharedMemorySize, F2_SMEM);

    const int T = 256;
    const int e_blk    = (e + T - 1) / T;
    const int fuse_blk = (n + 63) / 64;

    // ----- CSR build -----
    cudaMemsetAsync(cnt, 0, (size_t)n * sizeof(int));
    count_kernel<<<e_blk, T>>>(edst, e, cnt);
    scan_kernel<<<1, 1024>>>(cnt, off, cur, dinv, n);
    fill_kernel<<<e_blk, T>>>(esrc, edst, e, cur, srt);

    // ----- weight transposes -----
    transpose_kernel<DIN><<<dim3(DH / 32, DIN / 32), dim3(32, 8)>>>(W1, wt1);
    transpose_kernel<DH><<<dim3(DH / 32, DH / 32), dim3(32, 8)>>>(W2, wt2);

    // ----- Layer 1 fused: gather(x) + GEMM(W1) -> buf2 = hs (pre-scaled) -----
    fused_kernel<DIN, 1><<<fuse_blk, T, F1_SMEM>>>(x, wt1, off, srt, dinv, b1, buf2, n);

    // ----- Layer 2 fused: gather(hs) + GEMM(W2) -> out -----
    fused_kernel<DH, 2><<<fuse_blk, T, F2_SMEM>>>(buf2, wt2, off, srt, dinv, b2, out, n);
}